// round 1
// baseline (speedup 1.0000x reference)
#include <cuda_runtime.h>
#include <math.h>

// ---------------- scratch (__device__ globals; allocation-free) ----------------
__device__ __align__(256) float g_hidden[200000 * 128];  // relu(rel_emb@W2a+b2a) for ALL rels
__device__ __align__(256) float g_pre[1024 * 132];       // gathered MLP1 input (129 padded to 132)
__device__ __align__(256) float g_t1[1024 * 256];
__device__ __align__(256) float g_emb[1024 * 256];
__device__ __align__(256) float g_gates[1024 * 1024];
__device__ __align__(256) float g_t3[1024 * 128];
__device__ __align__(256) float g_aemb[1024 * 64];
__device__ __align__(256) float g_v[1024 * 128];         // W2b @ a_b per sample
__device__ __align__(256) float g_c[1024];               // a_b . b2b per sample

// ---------------- generic tiled GEMM: C = act(A@B (+A2@B2) + bias (+bias2)) ----
// A row-major [M, lda] using K cols; B row-major [K, N]. Tiles 64x128x32, 256 thr,
// 4x8 register micro-tile.
__global__ __launch_bounds__(256) void gemm_tiled(
    const float* __restrict__ A, int lda, int K,
    const float* __restrict__ B,
    const float* __restrict__ A2, int lda2, int K2,
    const float* __restrict__ B2,
    const float* __restrict__ bias, const float* __restrict__ bias2,
    float* __restrict__ C, int M, int N, int relu)
{
    __shared__ __align__(16) float As[32][68];    // transposed: As[k][m]
    __shared__ __align__(16) float Bs[32][132];   // Bs[k][n]

    const int tid = threadIdx.x;
    const int tn = tid & 15;        // 16 in n-dir (x8)
    const int tm = tid >> 4;        // 16 in m-dir (x4)
    const int m0 = blockIdx.x * 64;
    const int n0 = blockIdx.y * 128;

    float acc[4][8];
#pragma unroll
    for (int i = 0; i < 4; i++)
#pragma unroll
        for (int j = 0; j < 8; j++) acc[i][j] = 0.f;

    const int npass = (A2 != nullptr) ? 2 : 1;
    for (int pass = 0; pass < npass; ++pass) {
        const float* Ap = (pass == 0) ? A : A2;
        const float* Bp = (pass == 0) ? B : B2;
        const int Kc    = (pass == 0) ? K : K2;
        const int ldc   = (pass == 0) ? lda : lda2;

        for (int k0 = 0; k0 < Kc; k0 += 32) {
            // ---- load A tile (64 rows x 32 k), store transposed ----
#pragma unroll
            for (int it = 0; it < 2; ++it) {
                int f = tid + it * 256;
                int r = f >> 3;                // 0..63
                int c4 = (f & 7) << 2;         // 0..28
                int gk = k0 + c4;
                int grow = m0 + r;
                float4 v;
                if (gk + 3 < Kc) {
                    v = *(const float4*)(Ap + (size_t)grow * ldc + gk);
                } else {
                    v.x = (gk     < Kc) ? Ap[(size_t)grow * ldc + gk    ] : 0.f;
                    v.y = (gk + 1 < Kc) ? Ap[(size_t)grow * ldc + gk + 1] : 0.f;
                    v.z = (gk + 2 < Kc) ? Ap[(size_t)grow * ldc + gk + 2] : 0.f;
                    v.w = (gk + 3 < Kc) ? Ap[(size_t)grow * ldc + gk + 3] : 0.f;
                }
                As[c4    ][r] = v.x;
                As[c4 + 1][r] = v.y;
                As[c4 + 2][r] = v.z;
                As[c4 + 3][r] = v.w;
            }
            // ---- load B tile (32 k x 128 n) ----
#pragma unroll
            for (int it = 0; it < 4; ++it) {
                int f = tid + it * 256;
                int r = f >> 5;                // 0..31
                int c4 = (f & 31) << 2;        // 0..124
                int gk = k0 + r;
                int gn = n0 + c4;
                float4 v = make_float4(0.f, 0.f, 0.f, 0.f);
                if (gk < Kc && gn < N)
                    v = *(const float4*)(Bp + (size_t)gk * N + gn);
                *(float4*)&Bs[r][c4] = v;
            }
            __syncthreads();
#pragma unroll
            for (int kk = 0; kk < 32; ++kk) {
                float a[4], bb[8];
                *(float4*)&a[0]  = *(const float4*)&As[kk][tm << 2];
                *(float4*)&bb[0] = *(const float4*)&Bs[kk][tn << 3];
                *(float4*)&bb[4] = *(const float4*)&Bs[kk][(tn << 3) + 4];
#pragma unroll
                for (int i = 0; i < 4; i++)
#pragma unroll
                    for (int j = 0; j < 8; j++)
                        acc[i][j] += a[i] * bb[j];
            }
            __syncthreads();
        }
    }

    // ---- epilogue ----
#pragma unroll
    for (int i = 0; i < 4; i++) {
        int gm = m0 + (tm << 2) + i;
#pragma unroll
        for (int j = 0; j < 8; j++) {
            int gn = n0 + (tn << 3) + j;
            if (gm < M && gn < N) {
                float x = acc[i][j];
                if (bias)  x += bias[gn];
                if (bias2) x += bias2[gn];
                if (relu)  x = fmaxf(x, 0.f);
                C[(size_t)gm * N + gn] = x;
            }
        }
    }
}

// ---------------- gather MLP1 input: [node0 | node1 | t/200 | 0 0 0] ------------
__global__ void gather_pre(const float* __restrict__ node_emb,
                           const int* __restrict__ a0, const int* __restrict__ a1,
                           const float* __restrict__ states2, float* __restrict__ pre)
{
    int b = blockIdx.x;
    int t = threadIdx.x;  // 132
    float v;
    if (t < 64)        v = node_emb[(size_t)a0[b] * 64 + t];
    else if (t < 128)  v = node_emb[(size_t)a1[b] * 64 + (t - 64)];
    else if (t == 128) v = states2[b] * (1.0f / 200.0f);
    else               v = 0.f;
    pre[b * 132 + t] = v;
}

// ---------------- LSTM cell elementwise ----------------------------------------
__global__ void lstm_kernel(const float* __restrict__ gates, const float* __restrict__ c0,
                            float* __restrict__ out)
{
    int idx = blockIdx.x * blockDim.x + threadIdx.x;
    if (idx >= 1024 * 256) return;
    int b = idx >> 8;
    int h = idx & 255;
    const float* g = gates + (size_t)b * 1024;
    float gi = g[h], gf = g[256 + h], gg = g[512 + h], go = g[768 + h];
    float c = c0[idx];
    float si = 1.f / (1.f + expf(-gi));
    float sf = 1.f / (1.f + expf(-gf));
    float so = 1.f / (1.f + expf(-go));
    float cn = sf * c + si * tanhf(gg);
    float hn = so * tanhf(cn);
    out[524288 + idx]          = hn;  // h1
    out[524288 + 262144 + idx] = cn;  // c1
}

// ---------------- fold W2b into action embedding: v_b = W2b @ a_b ---------------
__global__ void compute_v(const float* __restrict__ aemb, const float* __restrict__ W2b,
                          const float* __restrict__ b2b, float* __restrict__ v,
                          float* __restrict__ cs)
{
    __shared__ float a[64];
    int b = blockIdx.x;
    int t = threadIdx.x;  // 128
    if (t < 64) a[t] = aemb[b * 64 + t];
    __syncthreads();
    float acc = 0.f;
#pragma unroll
    for (int n4 = 0; n4 < 16; ++n4) {
        float4 w = *(const float4*)(W2b + t * 64 + n4 * 4);
        acc += w.x * a[n4 * 4] + w.y * a[n4 * 4 + 1] + w.z * a[n4 * 4 + 2] + w.w * a[n4 * 4 + 3];
    }
    v[b * 128 + t] = acc;
    if (t == 0) {
        float c = 0.f;
#pragma unroll
        for (int n = 0; n < 64; ++n) c += a[n] * b2b[n];
        cs[b] = c;
    }
}

// ---------------- scoring: values[b,k] = (hidden[idx].v_b + c_b)/8 --------------
// groups of 8 lanes cooperatively read one 512B hidden row (coalesced 128B/phase)
__global__ __launch_bounds__(256) void score_kernel(
    const int* __restrict__ cand, const float* __restrict__ hidden,
    const float* __restrict__ v, const float* __restrict__ cs,
    float* __restrict__ out)
{
    int b = blockIdx.x;
    int l = threadIdx.x & 7;     // sub-lane in 8-group
    int grp = threadIdx.x >> 3;  // 0..31

    // per-lane slice of v_b in registers: words {j4*32 + l*4 .. +3}
    float vr[16];
#pragma unroll
    for (int j4 = 0; j4 < 4; ++j4) {
        float4 t = *(const float4*)(v + b * 128 + j4 * 32 + l * 4);
        vr[j4 * 4 + 0] = t.x; vr[j4 * 4 + 1] = t.y;
        vr[j4 * 4 + 2] = t.z; vr[j4 * 4 + 3] = t.w;
    }
    float cb = cs[b];

    for (int k = grp; k < 512; k += 32) {
        int idx = cand[b * 512 + k];
        const float4* row = (const float4*)(hidden + (size_t)idx * 128);
        float acc = 0.f;
#pragma unroll
        for (int j4 = 0; j4 < 4; ++j4) {
            float4 hv = row[j4 * 8 + l];   // 8 lanes -> 128B contiguous
            acc += hv.x * vr[j4 * 4 + 0] + hv.y * vr[j4 * 4 + 1]
                 + hv.z * vr[j4 * 4 + 2] + hv.w * vr[j4 * 4 + 3];
        }
        acc += __shfl_down_sync(0xffffffffu, acc, 4);
        acc += __shfl_down_sync(0xffffffffu, acc, 2);
        acc += __shfl_down_sync(0xffffffffu, acc, 1);
        if (l == 0) out[b * 512 + k] = (acc + cb) * 0.125f;
    }
}

// ---------------- launch --------------------------------------------------------
extern "C" void kernel_launch(void* const* d_in, const int* in_sizes, int n_in,
                              void* d_out, int out_size)
{
    const float* states2  = (const float*)d_in[0];
    const float* h0       = (const float*)d_in[1];
    const float* c0       = (const float*)d_in[2];
    const int*   actions0 = (const int*)d_in[3];
    const int*   actions1 = (const int*)d_in[4];
    const int*   cand     = (const int*)d_in[5];
    const float* node_emb = (const float*)d_in[6];
    const float* rel_emb  = (const float*)d_in[7];
    const float* W1a = (const float*)d_in[8];
    const float* b1a = (const float*)d_in[9];
    const float* W1b = (const float*)d_in[10];
    const float* b1b = (const float*)d_in[11];
    const float* W2a = (const float*)d_in[12];
    const float* b2a = (const float*)d_in[13];
    const float* W2b = (const float*)d_in[14];
    const float* b2b = (const float*)d_in[15];
    const float* W3a = (const float*)d_in[16];
    const float* b3a = (const float*)d_in[17];
    const float* W3b = (const float*)d_in[18];
    const float* b3b = (const float*)d_in[19];
    const float* W_ih = (const float*)d_in[20];
    const float* W_hh = (const float*)d_in[21];
    const float* b_ih = (const float*)d_in[22];
    const float* b_hh = (const float*)d_in[23];
    float* out = (float*)d_out;

    float *p_hidden, *p_pre, *p_t1, *p_emb, *p_gates, *p_t3, *p_aemb, *p_v, *p_c;
    cudaGetSymbolAddress((void**)&p_hidden, g_hidden);
    cudaGetSymbolAddress((void**)&p_pre,    g_pre);
    cudaGetSymbolAddress((void**)&p_t1,     g_t1);
    cudaGetSymbolAddress((void**)&p_emb,    g_emb);
    cudaGetSymbolAddress((void**)&p_gates,  g_gates);
    cudaGetSymbolAddress((void**)&p_t3,     g_t3);
    cudaGetSymbolAddress((void**)&p_aemb,   g_aemb);
    cudaGetSymbolAddress((void**)&p_v,      g_v);
    cudaGetSymbolAddress((void**)&p_c,      g_c);

    // 1) hidden_all = relu(rel_emb @ W2a + b2a)   [200000 x 128]
    gemm_tiled<<<dim3(3125, 1), 256>>>(rel_emb, 64, 64, W2a,
                                       nullptr, 0, 0, nullptr,
                                       b2a, nullptr, p_hidden, 200000, 128, 1);
    // 2) gather pre
    gather_pre<<<1024, 132>>>(node_emb, actions0, actions1, states2, p_pre);
    // 3) t1 = relu(pre @ W1a + b1a)
    gemm_tiled<<<dim3(16, 2), 256>>>(p_pre, 132, 129, W1a,
                                     nullptr, 0, 0, nullptr,
                                     b1a, nullptr, p_t1, 1024, 256, 1);
    // 4) emb = t1 @ W1b + b1b
    gemm_tiled<<<dim3(16, 2), 256>>>(p_t1, 256, 256, W1b,
                                     nullptr, 0, 0, nullptr,
                                     b1b, nullptr, p_emb, 1024, 256, 0);
    // 5) gates = emb @ W_ih + h0 @ W_hh + b_ih + b_hh
    gemm_tiled<<<dim3(16, 8), 256>>>(p_emb, 256, 256, W_ih,
                                     h0, 256, 256, W_hh,
                                     b_ih, b_hh, p_gates, 1024, 1024, 0);
    // 6) LSTM elementwise -> h1, c1 into out
    lstm_kernel<<<1024, 256>>>(p_gates, c0, out);
    // 7) t3 = relu(h1 @ W3a + b3a)
    gemm_tiled<<<dim3(16, 1), 256>>>(out + 524288, 256, 256, W3a,
                                     nullptr, 0, 0, nullptr,
                                     b3a, nullptr, p_t3, 1024, 128, 1);
    // 8) aemb = t3 @ W3b + b3b
    gemm_tiled<<<dim3(16, 1), 256>>>(p_t3, 128, 128, W3b,
                                     nullptr, 0, 0, nullptr,
                                     b3b, nullptr, p_aemb, 1024, 64, 0);
    // 9) v_b = W2b @ a_b ; c_b = a_b . b2b
    compute_v<<<1024, 128>>>(p_aemb, W2b, b2b, p_v, p_c);
    // 10) values
    score_kernel<<<1024, 256>>>(cand, p_hidden, p_v, p_c, out);
}

// round 3
// speedup vs baseline: 1.8026x; 1.8026x over previous
#include <cuda_runtime.h>
#include <cuda_fp16.h>
#include <mma.h>
#include <math.h>
#include <cstdint>

using namespace nvcuda;

// ================= scratch =================
__device__ __align__(256) float g_hidden[200000 * 128];
__device__ __align__(256) float g_pre[1024 * 132];
__device__ __align__(256) float g_t1[1024 * 256];
__device__ __align__(256) float g_emb[1024 * 256];
__device__ __align__(256) float g_gates[1024 * 1024];
__device__ __align__(256) float g_t3[1024 * 128];
__device__ __align__(256) float g_aemb[1024 * 64];
__device__ __align__(256) float g_v[1024 * 128];
__device__ __align__(256) float g_c[1024];

// ================= hidden precompute: wmma fp16 =================
// hidden[200000,128] = relu(rel_emb[200000,64] @ W2a[64,128] + b2a)
// Block: 256 thr (8 warps). Tile M=128, N=128, K=64. Warp w -> rows [16w,16w+16).
#define A_LD 72    // halves per A row (64 + 8 pad)
#define B_LD 136   // halves per B row (128 + 8 pad)
#define E_LD 68    // floats per epi row (64 + 4 pad)
#define H_SMEM_BYTES (128 * A_LD * 2 + 64 * B_LD * 2)   // 35840; epi (128*68*4=34816) aliases

__global__ __launch_bounds__(256) void hidden_wmma(
    const float* __restrict__ rel, const float* __restrict__ W2a,
    const float* __restrict__ b2a, float* __restrict__ hidden)
{
    extern __shared__ char smem[];
    __half* As = (__half*)smem;                       // [128][A_LD]
    __half* Bs = (__half*)(smem + 128 * A_LD * 2);    // [64][B_LD]
    float*  Es = (float*)smem;                        // [128][E_LD], reused after compute

    const int tid = threadIdx.x;
    const int wid = tid >> 5;
    const int m0 = blockIdx.x * 128;

    // ---- load A: 128 rows x 64 cols fp32 -> fp16 ----
#pragma unroll
    for (int e = tid; e < 128 * 32; e += 256) {       // float2 granules
        int row = e >> 5, c2 = (e & 31) << 1;
        int gr = m0 + row; if (gr > 199999) gr = 199999;
        float2 v = *(const float2*)(rel + (size_t)gr * 64 + c2);
        As[row * A_LD + c2]     = __float2half_rn(v.x);
        As[row * A_LD + c2 + 1] = __float2half_rn(v.y);
    }
    // ---- load B: W2a [64][128] fp32 -> fp16 ----
#pragma unroll
    for (int e = tid; e < 64 * 64; e += 256) {        // float2 granules
        int k = e >> 6, c2 = (e & 63) << 1;
        float2 v = *(const float2*)(W2a + (size_t)k * 128 + c2);
        Bs[k * B_LD + c2]     = __float2half_rn(v.x);
        Bs[k * B_LD + c2 + 1] = __float2half_rn(v.y);
    }
    __syncthreads();

    // ---- compute: warp strip 16 x 128 ----
    wmma::fragment<wmma::accumulator, 16, 16, 16, float> acc[8];
#pragma unroll
    for (int j = 0; j < 8; ++j) wmma::fill_fragment(acc[j], 0.0f);
#pragma unroll
    for (int k = 0; k < 4; ++k) {
        wmma::fragment<wmma::matrix_a, 16, 16, 16, __half, wmma::row_major> a;
        wmma::load_matrix_sync(a, As + wid * 16 * A_LD + k * 16, A_LD);
#pragma unroll
        for (int j = 0; j < 8; ++j) {
            wmma::fragment<wmma::matrix_b, 16, 16, 16, __half, wmma::row_major> b;
            wmma::load_matrix_sync(b, Bs + k * 16 * B_LD + j * 16, B_LD);
            wmma::mma_sync(acc[j], a, b, acc[j]);
        }
    }

    // ---- epilogue in two N-halves (keeps smem <= 35840B) ----
#pragma unroll
    for (int p = 0; p < 2; ++p) {
        __syncthreads();  // As/Bs fully consumed (p=0); prev half written (p=1)
#pragma unroll
        for (int jj = 0; jj < 4; ++jj)
            wmma::store_matrix_sync(Es + wid * 16 * E_LD + jj * 16, acc[p * 4 + jj],
                                    E_LD, wmma::mem_row_major);
        __syncthreads();
#pragma unroll
        for (int e = tid; e < 128 * 16; e += 256) {   // float4 granules over 64 cols
            int row = e >> 4, c4 = (e & 15) << 2;
            int gr = m0 + row;
            if (gr < 200000) {
                int gc = p * 64 + c4;
                float4 o;
                o.x = fmaxf(Es[row * E_LD + c4]     + b2a[gc],     0.f);
                o.y = fmaxf(Es[row * E_LD + c4 + 1] + b2a[gc + 1], 0.f);
                o.z = fmaxf(Es[row * E_LD + c4 + 2] + b2a[gc + 2], 0.f);
                o.w = fmaxf(Es[row * E_LD + c4 + 3] + b2a[gc + 3], 0.f);
                *(float4*)(hidden + (size_t)gr * 128 + gc) = o;
            }
        }
    }
}

// ================= small-batch GEMM: tile 32x64x32, 256 thr, 2x4 micro =================
__global__ __launch_bounds__(256) void gemm_small(
    const float* __restrict__ A, int lda, int K, const float* __restrict__ B,
    const float* __restrict__ A2, int lda2, int K2, const float* __restrict__ B2,
    const float* __restrict__ bias, const float* __restrict__ bias2,
    float* __restrict__ C, int M, int N, int relu)
{
    __shared__ __align__(16) float As[32][36];   // As[k][m]
    __shared__ __align__(16) float Bs[32][68];   // Bs[k][n]
    const int tid = threadIdx.x;
    const int tn = tid & 15, tm = tid >> 4;
    const int m0 = blockIdx.x * 32, n0 = blockIdx.y * 64;

    float acc[2][4];
#pragma unroll
    for (int i = 0; i < 2; i++)
#pragma unroll
        for (int j = 0; j < 4; j++) acc[i][j] = 0.f;

    const int npass = (A2 != nullptr) ? 2 : 1;
    for (int pass = 0; pass < npass; ++pass) {
        const float* Ap = (pass == 0) ? A : A2;
        const float* Bp = (pass == 0) ? B : B2;
        const int Kc    = (pass == 0) ? K : K2;
        const int ldc   = (pass == 0) ? lda : lda2;
        for (int k0 = 0; k0 < Kc; k0 += 32) {
            { // A tile: 32 rows x 32 k
                int r = tid >> 3, c4 = (tid & 7) << 2;
                int gk = k0 + c4, gr = m0 + r;
                float4 v = make_float4(0.f, 0.f, 0.f, 0.f);
                if (gr < M) {
                    if (gk + 3 < Kc) v = *(const float4*)(Ap + (size_t)gr * ldc + gk);
                    else {
                        if (gk     < Kc) v.x = Ap[(size_t)gr * ldc + gk    ];
                        if (gk + 1 < Kc) v.y = Ap[(size_t)gr * ldc + gk + 1];
                        if (gk + 2 < Kc) v.z = Ap[(size_t)gr * ldc + gk + 2];
                        if (gk + 3 < Kc) v.w = Ap[(size_t)gr * ldc + gk + 3];
                    }
                }
                As[c4][r] = v.x; As[c4 + 1][r] = v.y; As[c4 + 2][r] = v.z; As[c4 + 3][r] = v.w;
            }
#pragma unroll
            for (int it = 0; it < 2; ++it) { // B tile: 32 k x 64 n
                int f = tid + it * 256;
                int r = f >> 4, c4 = (f & 15) << 2;
                int gk = k0 + r, gn = n0 + c4;
                float4 v = make_float4(0.f, 0.f, 0.f, 0.f);
                if (gk < Kc && gn < N) v = *(const float4*)(Bp + (size_t)gk * N + gn);
                *(float4*)&Bs[r][c4] = v;
            }
            __syncthreads();
#pragma unroll
            for (int kk = 0; kk < 32; ++kk) {
                float a0 = As[kk][tm * 2], a1 = As[kk][tm * 2 + 1];
                float4 b = *(const float4*)&Bs[kk][tn * 4];
                acc[0][0] += a0 * b.x; acc[0][1] += a0 * b.y; acc[0][2] += a0 * b.z; acc[0][3] += a0 * b.w;
                acc[1][0] += a1 * b.x; acc[1][1] += a1 * b.y; acc[1][2] += a1 * b.z; acc[1][3] += a1 * b.w;
            }
            __syncthreads();
        }
    }
#pragma unroll
    for (int i = 0; i < 2; i++) {
        int gm = m0 + tm * 2 + i;
        if (gm >= M) continue;
#pragma unroll
        for (int j = 0; j < 4; j++) {
            int gn = n0 + tn * 4 + j;
            if (gn >= N) continue;
            float x = acc[i][j];
            if (bias)  x += bias[gn];
            if (bias2) x += bias2[gn];
            if (relu)  x = fmaxf(x, 0.f);
            C[(size_t)gm * N + gn] = x;
        }
    }
}

// ================= gather MLP1 input =================
__global__ void gather_pre(const float* __restrict__ node_emb,
                           const int* __restrict__ a0, const int* __restrict__ a1,
                           const float* __restrict__ states2, float* __restrict__ pre)
{
    int b = blockIdx.x;
    int t = threadIdx.x;  // 132
    float v;
    if (t < 64)        v = node_emb[(size_t)a0[b] * 64 + t];
    else if (t < 128)  v = node_emb[(size_t)a1[b] * 64 + (t - 64)];
    else if (t == 128) v = states2[b] * (1.0f / 200.0f);
    else               v = 0.f;
    pre[b * 132 + t] = v;
}

// ================= LSTM cell elementwise =================
__global__ void lstm_kernel(const float* __restrict__ gates, const float* __restrict__ c0,
                            float* __restrict__ out)
{
    int idx = blockIdx.x * blockDim.x + threadIdx.x;
    if (idx >= 1024 * 256) return;
    int b = idx >> 8;
    int h = idx & 255;
    const float* g = gates + (size_t)b * 1024;
    float gi = g[h], gf = g[256 + h], gg = g[512 + h], go = g[768 + h];
    float c = c0[idx];
    float si = 1.f / (1.f + expf(-gi));
    float sf = 1.f / (1.f + expf(-gf));
    float so = 1.f / (1.f + expf(-go));
    float cn = sf * c + si * tanhf(gg);
    float hn = so * tanhf(cn);
    out[524288 + idx]          = hn;
    out[524288 + 262144 + idx] = cn;
}

// ================= v_b = W2b @ a_b ; c_b = a_b . b2b =================
__global__ void compute_v(const float* __restrict__ aemb, const float* __restrict__ W2b,
                          const float* __restrict__ b2b, float* __restrict__ v,
                          float* __restrict__ cs)
{
    __shared__ float a[64];
    int b = blockIdx.x;
    int t = threadIdx.x;  // 128
    if (t < 64) a[t] = aemb[b * 64 + t];
    __syncthreads();
    float acc = 0.f;
#pragma unroll
    for (int n4 = 0; n4 < 16; ++n4) {
        float4 w = *(const float4*)(W2b + t * 64 + n4 * 4);
        acc += w.x * a[n4 * 4] + w.y * a[n4 * 4 + 1] + w.z * a[n4 * 4 + 2] + w.w * a[n4 * 4 + 3];
    }
    v[b * 128 + t] = acc;
    if (t == 0) {
        float c = 0.f;
#pragma unroll
        for (int n = 0; n < 64; ++n) c += a[n] * b2b[n];
        cs[b] = c;
    }
}

// ================= scoring =================
__global__ __launch_bounds__(256) void score_kernel(
    const int* __restrict__ cand, const float* __restrict__ hidden,
    const float* __restrict__ v, const float* __restrict__ cs,
    float* __restrict__ out)
{
    int b = blockIdx.x;
    int l = threadIdx.x & 7;
    int grp = threadIdx.x >> 3;

    float vr[16];
#pragma unroll
    for (int j4 = 0; j4 < 4; ++j4) {
        float4 t = *(const float4*)(v + b * 128 + j4 * 32 + l * 4);
        vr[j4 * 4 + 0] = t.x; vr[j4 * 4 + 1] = t.y;
        vr[j4 * 4 + 2] = t.z; vr[j4 * 4 + 3] = t.w;
    }
    float cb = cs[b];

    for (int k = grp; k < 512; k += 32) {
        int idx = cand[b * 512 + k];
        const float4* row = (const float4*)(hidden + (size_t)idx * 128);
        float acc = 0.f;
#pragma unroll
        for (int j4 = 0; j4 < 4; ++j4) {
            float4 hv = row[j4 * 8 + l];
            acc += hv.x * vr[j4 * 4 + 0] + hv.y * vr[j4 * 4 + 1]
                 + hv.z * vr[j4 * 4 + 2] + hv.w * vr[j4 * 4 + 3];
        }
        acc += __shfl_down_sync(0xffffffffu, acc, 4);
        acc += __shfl_down_sync(0xffffffffu, acc, 2);
        acc += __shfl_down_sync(0xffffffffu, acc, 1);
        if (l == 0) out[b * 512 + k] = (acc + cb) * 0.125f;
    }
}

// ================= launch =================
extern "C" void kernel_launch(void* const* d_in, const int* in_sizes, int n_in,
                              void* d_out, int out_size)
{
    const float* states2  = (const float*)d_in[0];
    const float* h0       = (const float*)d_in[1];
    const float* c0       = (const float*)d_in[2];
    const int*   actions0 = (const int*)d_in[3];
    const int*   actions1 = (const int*)d_in[4];
    const int*   cand     = (const int*)d_in[5];
    const float* node_emb = (const float*)d_in[6];
    const float* rel_emb  = (const float*)d_in[7];
    const float* W1a = (const float*)d_in[8];
    const float* b1a = (const float*)d_in[9];
    const float* W1b = (const float*)d_in[10];
    const float* b1b = (const float*)d_in[11];
    const float* W2a = (const float*)d_in[12];
    const float* b2a = (const float*)d_in[13];
    const float* W2b = (const float*)d_in[14];
    const float* b2b = (const float*)d_in[15];
    const float* W3a = (const float*)d_in[16];
    const float* b3a = (const float*)d_in[17];
    const float* W3b = (const float*)d_in[18];
    const float* b3b = (const float*)d_in[19];
    const float* W_ih = (const float*)d_in[20];
    const float* W_hh = (const float*)d_in[21];
    const float* b_ih = (const float*)d_in[22];
    const float* b_hh = (const float*)d_in[23];
    float* out = (float*)d_out;

    float *p_hidden, *p_pre, *p_t1, *p_emb, *p_gates, *p_t3, *p_aemb, *p_v, *p_c;
    cudaGetSymbolAddress((void**)&p_hidden, g_hidden);
    cudaGetSymbolAddress((void**)&p_pre,    g_pre);
    cudaGetSymbolAddress((void**)&p_t1,     g_t1);
    cudaGetSymbolAddress((void**)&p_emb,    g_emb);
    cudaGetSymbolAddress((void**)&p_gates,  g_gates);
    cudaGetSymbolAddress((void**)&p_t3,     g_t3);
    cudaGetSymbolAddress((void**)&p_aemb,   g_aemb);
    cudaGetSymbolAddress((void**)&p_v,      g_v);
    cudaGetSymbolAddress((void**)&p_c,      g_c);

    // 1) hidden_all = relu(rel_emb @ W2a + b2a) via wmma fp16  [200000 x 128]
    hidden_wmma<<<1563, 256, H_SMEM_BYTES>>>(rel_emb, W2a, b2a, p_hidden);
    // 2) gather pre
    gather_pre<<<1024, 132>>>(node_emb, actions0, actions1, states2, p_pre);
    // 3) t1 = relu(pre @ W1a + b1a)
    gemm_small<<<dim3(32, 4), 256>>>(p_pre, 132, 129, W1a, nullptr, 0, 0, nullptr,
                                     b1a, nullptr, p_t1, 1024, 256, 1);
    // 4) emb = t1 @ W1b + b1b
    gemm_small<<<dim3(32, 4), 256>>>(p_t1, 256, 256, W1b, nullptr, 0, 0, nullptr,
                                     b1b, nullptr, p_emb, 1024, 256, 0);
    // 5) gates = emb @ W_ih + h0 @ W_hh + b_ih + b_hh
    gemm_small<<<dim3(32, 16), 256>>>(p_emb, 256, 256, W_ih, h0, 256, 256, W_hh,
                                      b_ih, b_hh, p_gates, 1024, 1024, 0);
    // 6) LSTM elementwise -> h1, c1
    lstm_kernel<<<1024, 256>>>(p_gates, c0, out);
    // 7) t3 = relu(h1 @ W3a + b3a)
    gemm_small<<<dim3(32, 2), 256>>>(out + 524288, 256, 256, W3a, nullptr, 0, 0, nullptr,
                                     b3a, nullptr, p_t3, 1024, 128, 1);
    // 8) aemb = t3 @ W3b + b3b
    gemm_small<<<dim3(32, 1), 256>>>(p_t3, 128, 128, W3b, nullptr, 0, 0, nullptr,
                                     b3b, nullptr, p_aemb, 1024, 64, 0);
    // 9) v_b = W2b @ a_b ; c_b = a_b . b2b
    compute_v<<<1024, 128>>>(p_aemb, W2b, b2b, p_v, p_c);
    // 10) values
    score_kernel<<<1024, 256>>>(cand, p_hidden, p_v, p_c, out);
}